// round 15
// baseline (speedup 1.0000x reference)
#include <cuda_runtime.h>
#include <cuda_fp16.h>
#include <math.h>

#define NN 50000
#define MM 12
#define AA 64
#define NBRD 41
#define TWOA 128
#define BB 1000
#define NPCC 50
#define ORIG 92
#define RTOT (NN*MM)          // 600000 edge rows
#define EPSB 1e-5f
#define NFS_STRIDE 44

typedef unsigned long long ull;

// ---------------- device scratch ----------------
__device__ float  g_x[NN*AA];
__device__ float  g_summed[NN*AA];
__device__ float  g_P1[NN*TWOA];
__device__ float  g_P2[NN*TWOA];
__device__ __half g_gatedh[(size_t)RTOT*TWOA];   // 153 MB fp16
__device__ double g_sum1[3][TWOA], g_sumsq1[3][TWOA];
__device__ double g_sum2[3][AA],   g_sumsq2[3][AA];
__device__ float  g_logp[BB*NPCC*6];

// ---------------- f32x2 helpers ----------------
__device__ __forceinline__ ull f2x_pack(float lo, float hi) {
    ull r; asm("mov.b64 %0, {%1, %2};" : "=l"(r) : "f"(lo), "f"(hi)); return r;
}
__device__ __forceinline__ void f2x_unpack(ull v, float& lo, float& hi) {
    asm("mov.b64 {%0, %1}, %2;" : "=f"(lo), "=f"(hi) : "l"(v));
}
__device__ __forceinline__ ull f2x_fma(ull a, ull b, ull c) {
    ull d; asm("fma.rn.f32x2 %0, %1, %2, %3;" : "=l"(d) : "l"(a), "l"(b), "l"(c)); return d;
}
__device__ __forceinline__ ull f2x_add(ull a, ull b) {
    ull d; asm("add.rn.f32x2 %0, %1, %2;" : "=l"(d) : "l"(a), "l"(b)); return d;
}

// ---------------- fast math ----------------
__device__ __forceinline__ float softplus_fast(float x) {
    return fmaxf(x, 0.0f) + __logf(1.0f + __expf(-fabsf(x)));
}
__device__ __forceinline__ float sigmoid_fast(float x) {
    return __fdividef(1.0f, 1.0f + __expf(-x));
}

// ---------------- kernels ----------------
// x = atom_fea @ emb_w ; block 0 also zeroes the stat accumulators
__global__ __launch_bounds__(256)
void k_embed(const float* __restrict__ afea, const float* __restrict__ embw) {
    __shared__ float ws[ORIG*AA];
    __shared__ float xs[16*ORIG];
    int tid = threadIdx.x;
    if (blockIdx.x == 0) {
        for (int i = tid; i < 3*TWOA; i += 256) { (&g_sum1[0][0])[i] = 0.0; (&g_sumsq1[0][0])[i] = 0.0; }
        for (int i = tid; i < 3*AA;   i += 256) { (&g_sum2[0][0])[i] = 0.0; (&g_sumsq2[0][0])[i] = 0.0; }
    }
    int t = tid & 63, r4 = tid >> 6;
    for (int i = tid; i < ORIG*AA; i += 256) ws[i] = embw[i];
    __syncthreads();
    const int NG = NN / 16;
    for (int g = blockIdx.x; g < NG; g += gridDim.x) {
        int n0 = g * 16;
        for (int i = tid; i < 16*ORIG; i += 256) xs[i] = afea[(size_t)n0*ORIG + i];
        __syncthreads();
        const float* xb = &xs[r4*4*ORIG];
        float a0 = 0.f, a1 = 0.f, a2 = 0.f, a3 = 0.f;
        #pragma unroll 4
        for (int k = 0; k < ORIG; k++) {
            float w = ws[k*AA + t];
            a0 += xb[k]*w; a1 += xb[ORIG+k]*w; a2 += xb[2*ORIG+k]*w; a3 += xb[3*ORIG+k]*w;
        }
        int nb = n0 + r4*4;
        g_x[(size_t)(nb+0)*AA + t] = a0;
        g_x[(size_t)(nb+1)*AA + t] = a1;
        g_x[(size_t)(nb+2)*AA + t] = a2;
        g_x[(size_t)(nb+3)*AA + t] = a3;
        __syncthreads();
    }
}

// P1/P2 projection — weights via LDG (L1/L2-resident), no weight smem.
__global__ __launch_bounds__(256)
void k_proj(const float* __restrict__ w, const float* __restrict__ bias) {
    __shared__ float xs[32*AA];
    int tid = threadIdx.x;
    int t = tid & 63, r8 = tid >> 6;
    ull bc = f2x_pack(bias[2*t], bias[2*t+1]);
    const ull* wv = (const ull*)w;
    const int NG = (NN + 31) / 32;
    for (int g = blockIdx.x; g < NG; g += gridDim.x) {
        int n0 = g * 32;
        int cnt = min(32, NN - n0);
        for (int i = tid; i < cnt*AA; i += 256) xs[i] = g_x[(size_t)n0*AA + i];
        __syncthreads();
        const float* xb = &xs[r8*8*AA];
        int nb = n0 + r8*8;
        ull p1[8], p2[8];
        #pragma unroll
        for (int r = 0; r < 8; r++) { p1[r] = bc; p2[r] = 0ull; }
        #pragma unroll 4
        for (int a = 0; a < AA; a++) {
            ull w1 = __ldg(&wv[a*64 + t]);
            ull w2 = __ldg(&wv[(AA+a)*64 + t]);
            #pragma unroll
            for (int r = 0; r < 8; r++) {
                float xf = xb[r*AA + a];
                ull xv = f2x_pack(xf, xf);
                p1[r] = f2x_fma(xv, w1, p1[r]);
                p2[r] = f2x_fma(xv, w2, p2[r]);
            }
        }
        #pragma unroll
        for (int r = 0; r < 8; r++) {
            if (nb + r < NN) {
                ((ull*)&g_P1[(size_t)(nb+r)*TWOA])[t] = p1[r];
                ((ull*)&g_P2[(size_t)(nb+r)*TWOA])[t] = p2[r];
            }
        }
        __syncthreads();
    }
}

// gated = P1[n] + P2[nbr] + nbr_fea @ W_edge ; bn1 stats (fp32 exact); store fp16.
__global__ __launch_bounds__(256, 3)
void k_edge(const float* __restrict__ we, const float* __restrict__ nbrf,
            const int* __restrict__ nidx, int layer) {
    __shared__ ulonglong2 wsv[NBRD*32];
    __shared__ float  nfs[8][6*NFS_STRIDE];
    __shared__ float  redS[TWOA], redQ[TWOA];
    int tid = threadIdx.x;
    {
        float* wf = (float*)wsv;
        for (int i = tid; i < NBRD*TWOA; i += 256) wf[i] = we[i];
    }
    __syncthreads();

    int w    = tid >> 5;
    int lane = tid & 31;
    int wg   = blockIdx.x * 8 + w;
    int nw   = gridDim.x * 8;

    ull s01 = 0ull, s23 = 0ull, q01 = 0ull, q23 = 0ull;

    const int NCH = RTOT/6;
    for (int ch = wg; ch < NCH; ch += nw) {
        int r0 = ch * 6;
        int n  = ch >> 1;
        const float* src = &nbrf[(size_t)r0 * NBRD];
        #pragma unroll
        for (int i = 0; i < 8; i++) {
            int p = lane + i*32;
            if (p < 6*NBRD) {
                int rr = p / NBRD, kk = p - rr*NBRD;
                nfs[w][rr*NFS_STRIDE + kk] = src[p];
            }
        }
        __syncwarp();
        ulonglong2 pa = ((const ulonglong2*)&g_P1[(size_t)n*TWOA])[lane];
        ull a01[6], a23[6];
        #pragma unroll
        for (int rr = 0; rr < 6; rr++) {
            int j = nidx[r0 + rr];
            ulonglong2 pb = ((const ulonglong2*)&g_P2[(size_t)j*TWOA])[lane];
            a01[rr] = f2x_add(pa.x, pb.x);
            a23[rr] = f2x_add(pa.y, pb.y);
        }
        #pragma unroll 1
        for (int kb = 0; kb < 40; kb += 4) {
            ulonglong2 w0 = wsv[(kb+0)*32 + lane];
            ulonglong2 w1 = wsv[(kb+1)*32 + lane];
            ulonglong2 w2 = wsv[(kb+2)*32 + lane];
            ulonglong2 w3 = wsv[(kb+3)*32 + lane];
            #pragma unroll
            for (int rr = 0; rr < 6; rr++) {
                float4 f = *(const float4*)&nfs[w][rr*NFS_STRIDE + kb];
                ull fx = f2x_pack(f.x, f.x);
                ull fy = f2x_pack(f.y, f.y);
                ull fz = f2x_pack(f.z, f.z);
                ull fw = f2x_pack(f.w, f.w);
                a01[rr] = f2x_fma(fx, w0.x, a01[rr]); a23[rr] = f2x_fma(fx, w0.y, a23[rr]);
                a01[rr] = f2x_fma(fy, w1.x, a01[rr]); a23[rr] = f2x_fma(fy, w1.y, a23[rr]);
                a01[rr] = f2x_fma(fz, w2.x, a01[rr]); a23[rr] = f2x_fma(fz, w2.y, a23[rr]);
                a01[rr] = f2x_fma(fw, w3.x, a01[rr]); a23[rr] = f2x_fma(fw, w3.y, a23[rr]);
            }
        }
        {
            ulonglong2 w4 = wsv[40*32 + lane];
            #pragma unroll
            for (int rr = 0; rr < 6; rr++) {
                float f = nfs[w][rr*NFS_STRIDE + 40];
                ull ff = f2x_pack(f, f);
                a01[rr] = f2x_fma(ff, w4.x, a01[rr]);
                a23[rr] = f2x_fma(ff, w4.y, a23[rr]);
            }
        }
        #pragma unroll
        for (int rr = 0; rr < 6; rr++) {
            float x0, x1, x2, x3;
            f2x_unpack(a01[rr], x0, x1);
            f2x_unpack(a23[rr], x2, x3);
            __half2 h0 = __floats2half2_rn(x0, x1);
            __half2 h1 = __floats2half2_rn(x2, x3);
            uint2 st; st.x = *(unsigned*)&h0; st.y = *(unsigned*)&h1;
            *(uint2*)&g_gatedh[(size_t)(r0+rr)*TWOA + lane*4] = st;
            s01 = f2x_add(s01, a01[rr]);
            s23 = f2x_add(s23, a23[rr]);
            q01 = f2x_fma(a01[rr], a01[rr], q01);
            q23 = f2x_fma(a23[rr], a23[rr], q23);
        }
        __syncwarp();
    }

    float s0,s1,s2,s3,q0,q1,q2,q3;
    f2x_unpack(s01, s0, s1); f2x_unpack(s23, s2, s3);
    f2x_unpack(q01, q0, q1); f2x_unpack(q23, q2, q3);

    if (tid < TWOA) { redS[tid] = 0.f; redQ[tid] = 0.f; }
    __syncthreads();
    int c = lane * 4;
    atomicAdd(&redS[c+0], s0); atomicAdd(&redQ[c+0], q0);
    atomicAdd(&redS[c+1], s1); atomicAdd(&redQ[c+1], q1);
    atomicAdd(&redS[c+2], s2); atomicAdd(&redQ[c+2], q2);
    atomicAdd(&redS[c+3], s3); atomicAdd(&redQ[c+3], q3);
    __syncthreads();
    if (tid < TWOA) {
        atomicAdd(&g_sum1[layer][tid],   (double)redS[tid]);
        atomicAdd(&g_sumsq1[layer][tid], (double)redQ[tid]);
    }
}

// bn1 (prologue) -> sigmoid*softplus -> sum over M ; bn2 stats. (R8 16x16 mapping)
__global__ __launch_bounds__(256)
void k_apply(int layer, const float* __restrict__ bn1g, const float* __restrict__ bn1b) {
    __shared__ float scS[TWOA], shS[TWOA];
    int tid = threadIdx.x;
    if (tid < TWOA) {
        double mean = g_sum1[layer][tid] * (1.0 / (double)RTOT);
        double var  = g_sumsq1[layer][tid] * (1.0 / (double)RTOT) - mean * mean;
        float istd = rsqrtf((float)var + EPSB);
        float sc = istd * bn1g[tid];
        scS[tid] = sc;
        shS[tid] = bn1b[tid] - (float)mean * sc;
    }
    __syncthreads();

    int tx = tid & 15, ty = tid >> 4;
    int c0 = tx * 4;
    float4 scF = *(const float4*)&scS[c0];
    float4 shF = *(const float4*)&shS[c0];
    float4 scC = *(const float4*)&scS[AA + c0];
    float4 shC = *(const float4*)&shS[AA + c0];
    float ls0=0,ls1=0,ls2=0,ls3=0, lq0=0,lq1=0,lq2=0,lq3=0;
    for (int n = blockIdx.x*16 + ty; n < NN; n += gridDim.x*16) {
        const uint2* gp = (const uint2*)&g_gatedh[(size_t)n*(MM*TWOA)];
        float s0=0,s1=0,s2=0,s3=0;
        #pragma unroll
        for (int m = 0; m < MM; m++) {
            uint2 fraw = gp[m*32 + tx];
            uint2 craw = gp[m*32 + 16 + tx];
            float2 f01 = __half22float2(*(__half2*)&fraw.x);
            float2 f23 = __half22float2(*(__half2*)&fraw.y);
            float2 c01 = __half22float2(*(__half2*)&craw.x);
            float2 c23 = __half22float2(*(__half2*)&craw.y);
            s0 += sigmoid_fast(f01.x*scF.x + shF.x) * softplus_fast(c01.x*scC.x + shC.x);
            s1 += sigmoid_fast(f01.y*scF.y + shF.y) * softplus_fast(c01.y*scC.y + shC.y);
            s2 += sigmoid_fast(f23.x*scF.z + shF.z) * softplus_fast(c23.x*scC.z + shC.z);
            s3 += sigmoid_fast(f23.y*scF.w + shF.w) * softplus_fast(c23.y*scC.w + shC.w);
        }
        float4 outv; outv.x=s0; outv.y=s1; outv.z=s2; outv.w=s3;
        *(float4*)&g_summed[(size_t)n*AA + c0] = outv;
        ls0+=s0; lq0+=s0*s0; ls1+=s1; lq1+=s1*s1;
        ls2+=s2; lq2+=s2*s2; ls3+=s3; lq3+=s3*s3;
    }
    __shared__ float rS[AA], rQ[AA];
    if (ty == 0) {
        #pragma unroll
        for (int i = 0; i < 4; i++) { rS[c0+i] = 0.f; rQ[c0+i] = 0.f; }
    }
    __syncthreads();
    atomicAdd(&rS[c0+0], ls0); atomicAdd(&rQ[c0+0], lq0);
    atomicAdd(&rS[c0+1], ls1); atomicAdd(&rQ[c0+1], lq1);
    atomicAdd(&rS[c0+2], ls2); atomicAdd(&rQ[c0+2], lq2);
    atomicAdd(&rS[c0+3], ls3); atomicAdd(&rQ[c0+3], lq3);
    __syncthreads();
    if (ty == 0) {
        #pragma unroll
        for (int i = 0; i < 4; i++) {
            atomicAdd(&g_sum2[layer][c0+i],   (double)rS[c0+i]);
            atomicAdd(&g_sumsq2[layer][c0+i], (double)rQ[c0+i]);
        }
    }
}

// x = softplus(x + bn2(summed))
__global__ __launch_bounds__(256)
void k_update(int layer, const float* __restrict__ bn2g, const float* __restrict__ bn2b) {
    __shared__ float sc2[AA], sh2[AA];
    int tid = threadIdx.x;
    if (tid < AA) {
        double mean = g_sum2[layer][tid] * (1.0 / (double)NN);
        double var  = g_sumsq2[layer][tid] * (1.0 / (double)NN) - mean * mean;
        float istd = rsqrtf((float)var + EPSB);
        float sc = istd * bn2g[tid];
        sc2[tid] = sc;
        sh2[tid] = bn2b[tid] - (float)mean * sc;
    }
    __syncthreads();
    const int NV = NN*AA/4;
    for (int i4 = blockIdx.x*256 + tid; i4 < NV; i4 += gridDim.x*256) {
        int c0 = (i4 & 15) * 4;
        float4 xv = *(const float4*)&g_x[(size_t)i4*4];
        float4 sv = *(const float4*)&g_summed[(size_t)i4*4];
        float4 o;
        o.x = softplus_fast(xv.x + sv.x*sc2[c0+0] + sh2[c0+0]);
        o.y = softplus_fast(xv.y + sv.y*sc2[c0+1] + sh2[c0+1]);
        o.z = softplus_fast(xv.z + sv.z*sc2[c0+2] + sh2[c0+2]);
        o.w = softplus_fast(xv.w + sv.w*sc2[c0+3] + sh2[c0+3]);
        *(float4*)&g_x[(size_t)i4*4] = o;
    }
}

// Final stage v2: warp owns groups of 2 atoms; smem = Wt + vst + qsh only
// (~105 KB) so 2 blocks/SM = 32 warps; afw read via __ldg (L1-resident).
__global__ __launch_bounds__(512, 2)
void k_final(const int* __restrict__ cidx,
             const float* __restrict__ adjw, const float* __restrict__ adjb,
             const float* __restrict__ fc1w, const float* __restrict__ fc1b,
             const float* __restrict__ afw,  const float* __restrict__ afb,
             float* __restrict__ out2) {
    extern __shared__ float smem[];
    float* Wt  = smem;                     // 24576 floats: Wt[o][e][d] = adjw[o][d][e]
    float* vst = Wt + 6*64*64;             // 16*2*64 = 2048
    float* qsh = vst + 16*2*64;            // 16*2*6  = 192
    int tid = threadIdx.x;
    int w = tid >> 5, lane = tid & 31;
    for (int i = tid; i < 6*64*64; i += 512) {
        int o = i >> 12, rem = i & 4095, e = rem >> 6, d = rem & 63;
        Wt[i] = adjw[o*4096 + d*64 + e];
    }
    __syncthreads();

    float* vw = &vst[w*2*64];
    float* qw = &qsh[w*2*6];
    ull bias0 = *(const ull*)&afb[2*lane];
    ull bias1 = (lane < 14) ? *(const ull*)&afb[64 + 2*lane] : 0ull;
    const ull* afv = (const ull*)afw;      // afw element-pairs; row stride 92 floats = 46 ull

    int nwarps = gridDim.x * 16;
    int wgid   = blockIdx.x * 16 + w;
    for (int g0 = wgid*2; g0 < BB*NPCC; g0 += nwarps*2) {
        #pragma unroll
        for (int t = 0; t < 2; t++) {
            int idx = cidx[g0 + t];
            vw[t*64 + lane]      = g_x[(size_t)idx*AA + lane];
            vw[t*64 + lane + 32] = g_x[(size_t)idx*AA + lane + 32];
        }
        __syncwarp();
        float2 rv[2];
        #pragma unroll
        for (int t = 0; t < 2; t++) rv[t] = *(const float2*)&vw[t*64 + 2*lane];

        ull acc[2][6];
        #pragma unroll
        for (int t = 0; t < 2; t++)
            #pragma unroll
            for (int o = 0; o < 6; o++) acc[t][o] = 0ull;
        #pragma unroll 2
        for (int e = 0; e < 64; e++) {
            ull wv[6];
            #pragma unroll
            for (int o = 0; o < 6; o++) wv[o] = *(const ull*)&Wt[(o*64 + e)*64 + 2*lane];
            #pragma unroll
            for (int t = 0; t < 2; t++) {
                float vb = vw[t*64 + e];
                ull vbb = f2x_pack(vb, vb);
                #pragma unroll
                for (int o = 0; o < 6; o++) acc[t][o] = f2x_fma(vbb, wv[o], acc[t][o]);
            }
        }
        #pragma unroll
        for (int t = 0; t < 2; t++) {
            #pragma unroll
            for (int o = 0; o < 6; o++) {
                float lo, hi; f2x_unpack(acc[t][o], lo, hi);
                float p = lo * rv[t].x + hi * rv[t].y;
                #pragma unroll
                for (int off = 16; off; off >>= 1) p += __shfl_xor_sync(0xffffffffu, p, off);
                if (lane == 0) qw[t*6 + o] = p + adjb[o];
            }
        }
        __syncwarp();
        if (lane < 2) {
            int t = lane;
            float q[6], q2[6];
            #pragma unroll
            for (int o = 0; o < 6; o++) q[o] = qw[t*6 + o];
            #pragma unroll
            for (int j = 0; j < 6; j++) {
                float a = fc1b[j];
                #pragma unroll
                for (int o = 0; o < 6; o++) a += q[o] * fc1w[o*6 + j];
                q2[j] = a;
            }
            float mx = q2[0];
            #pragma unroll
            for (int j = 1; j < 6; j++) mx = fmaxf(mx, q2[j]);
            float se = 0.f;
            #pragma unroll
            for (int j = 0; j < 6; j++) se += __expf(q2[j] - mx);
            float lse = __logf(se);
            #pragma unroll
            for (int j = 0; j < 6; j++) g_logp[(g0 + t)*6 + j] = q2[j] - mx - lse;
        }
        {
            ull acc0[2], acc1[2];
            #pragma unroll
            for (int t = 0; t < 2; t++) { acc0[t] = bias0; acc1[t] = bias1; }
            #pragma unroll 2
            for (int a = 0; a < 64; a++) {
                ull w0 = __ldg(&afv[a*46 + lane]);
                ull w1 = (lane < 14) ? __ldg(&afv[a*46 + 32 + lane]) : 0ull;
                #pragma unroll
                for (int t = 0; t < 2; t++) {
                    float va = vw[t*64 + a];
                    ull vv = f2x_pack(va, va);
                    acc0[t] = f2x_fma(vv, w0, acc0[t]);
                    acc1[t] = f2x_fma(vv, w1, acc1[t]);
                }
            }
            #pragma unroll
            for (int t = 0; t < 2; t++) {
                *(ull*)&out2[(size_t)(g0+t)*ORIG + 2*lane] = acc0[t];
                if (lane < 14) *(ull*)&out2[(size_t)(g0+t)*ORIG + 64 + 2*lane] = acc1[t];
            }
        }
        __syncwarp();
    }
}

// edge_prob broadcast — float4 stores
__global__ __launch_bounds__(256)
void k_edgeprob(float* __restrict__ out) {
    __shared__ float sh[NPCC*6];
    int b = blockIdx.x;
    for (int i = threadIdx.x; i < NPCC*6; i += 256) sh[i] = g_logp[b*NPCC*6 + i];
    __syncthreads();
    const float4* s4 = (const float4*)sh;
    float4* o4 = (float4*)(out + (size_t)b * (NPCC*NPCC*6));
    const int NT = NPCC*NPCC*6/4;
    for (int t = threadIdx.x; t < NT; t += 256) o4[t] = s4[t % 75];
}

// ---------------- host ----------------
extern "C" void kernel_launch(void* const* d_in, const int* in_sizes, int n_in,
                              void* d_out, int out_size) {
    const float* atom_fea = (const float*)d_in[0];
    const float* nbr_fea  = (const float*)d_in[1];
    const int*   nbr_idx  = (const int*)  d_in[2];
    const int*   cidx     = (const int*)  d_in[3];
    const float* emb_w    = (const float*)d_in[4];
    const float* fcw      = (const float*)d_in[5];
    const float* fcb      = (const float*)d_in[6];
    const float* bn1g     = (const float*)d_in[7];
    const float* bn1b     = (const float*)d_in[8];
    const float* bn2g     = (const float*)d_in[9];
    const float* bn2b     = (const float*)d_in[10];
    const float* adjw     = (const float*)d_in[11];
    const float* adjb     = (const float*)d_in[12];
    const float* fc1w     = (const float*)d_in[13];
    const float* fc1b     = (const float*)d_in[14];
    const float* afw      = (const float*)d_in[15];
    const float* afb      = (const float*)d_in[16];
    float* out = (float*)d_out;

    const int FINAL_SMEM = (6*64*64 + 16*2*64 + 16*2*6) * sizeof(float);   // ~104.8 KB
    cudaFuncSetAttribute(k_final, cudaFuncAttributeMaxDynamicSharedMemorySize, FINAL_SMEM);

    k_embed<<<1184, 256>>>(atom_fea, emb_w);

    for (int i = 0; i < 3; i++) {
        const float* w = fcw + i * (2*AA + NBRD) * TWOA;
        k_proj<<<592, 256>>>(w, fcb + i*TWOA);
        k_edge<<<444, 256>>>(w + 2*AA*TWOA, nbr_fea, nbr_idx, i);
        k_apply<<<1184, 256>>>(i, bn1g + i*TWOA, bn1b + i*TWOA);
        k_update<<<592, 256>>>(i, bn2g + i*AA, bn2b + i*AA);
    }

    float* out_atomfea = out + (size_t)BB * NPCC * NPCC * 6;
    k_final<<<296, 512, FINAL_SMEM>>>(cidx, adjw, adjb, fc1w, fc1b, afw, afb, out_atomfea);
    k_edgeprob<<<BB, 256>>>(out);
}

// round 16
// speedup vs baseline: 1.0547x; 1.0547x over previous
#include <cuda_runtime.h>
#include <cuda_fp16.h>
#include <math.h>

#define NN 50000
#define MM 12
#define AA 64
#define NBRD 41
#define TWOA 128
#define BB 1000
#define NPCC 50
#define ORIG 92
#define RTOT (NN*MM)          // 600000 edge rows
#define EPSB 1e-5f
#define NFS_STRIDE 44

typedef unsigned long long ull;

// ---------------- device scratch ----------------
__device__ float  g_x[NN*AA];
__device__ float  g_summed[NN*AA];
__device__ float  g_P1[NN*TWOA];
__device__ float  g_P2[NN*TWOA];
__device__ __half g_gatedh[(size_t)RTOT*TWOA];   // 153 MB fp16
__device__ double g_sum1[3][TWOA], g_sumsq1[3][TWOA];
__device__ double g_sum2[3][AA],   g_sumsq2[3][AA];
__device__ float  g_logp[BB*NPCC*6];

// ---------------- f32x2 helpers ----------------
__device__ __forceinline__ ull f2x_pack(float lo, float hi) {
    ull r; asm("mov.b64 %0, {%1, %2};" : "=l"(r) : "f"(lo), "f"(hi)); return r;
}
__device__ __forceinline__ void f2x_unpack(ull v, float& lo, float& hi) {
    asm("mov.b64 {%0, %1}, %2;" : "=f"(lo), "=f"(hi) : "l"(v));
}
__device__ __forceinline__ ull f2x_fma(ull a, ull b, ull c) {
    ull d; asm("fma.rn.f32x2 %0, %1, %2, %3;" : "=l"(d) : "l"(a), "l"(b), "l"(c)); return d;
}
__device__ __forceinline__ ull f2x_add(ull a, ull b) {
    ull d; asm("add.rn.f32x2 %0, %1, %2;" : "=l"(d) : "l"(a), "l"(b)); return d;
}

// ---------------- fast math ----------------
__device__ __forceinline__ float softplus_fast(float x) {
    return fmaxf(x, 0.0f) + __logf(1.0f + __expf(-fabsf(x)));
}
__device__ __forceinline__ float sigmoid_fast(float x) {
    return __fdividef(1.0f, 1.0f + __expf(-x));
}

// ---------------- kernels ----------------
// x = atom_fea @ emb_w ; block 0 also zeroes the stat accumulators
__global__ __launch_bounds__(256)
void k_embed(const float* __restrict__ afea, const float* __restrict__ embw) {
    __shared__ float ws[ORIG*AA];
    __shared__ float xs[16*ORIG];
    int tid = threadIdx.x;
    if (blockIdx.x == 0) {
        for (int i = tid; i < 3*TWOA; i += 256) { (&g_sum1[0][0])[i] = 0.0; (&g_sumsq1[0][0])[i] = 0.0; }
        for (int i = tid; i < 3*AA;   i += 256) { (&g_sum2[0][0])[i] = 0.0; (&g_sumsq2[0][0])[i] = 0.0; }
    }
    int t = tid & 63, r4 = tid >> 6;
    for (int i = tid; i < ORIG*AA; i += 256) ws[i] = embw[i];
    __syncthreads();
    const int NG = NN / 16;
    for (int g = blockIdx.x; g < NG; g += gridDim.x) {
        int n0 = g * 16;
        for (int i = tid; i < 16*ORIG; i += 256) xs[i] = afea[(size_t)n0*ORIG + i];
        __syncthreads();
        const float* xb = &xs[r4*4*ORIG];
        float a0 = 0.f, a1 = 0.f, a2 = 0.f, a3 = 0.f;
        #pragma unroll 4
        for (int k = 0; k < ORIG; k++) {
            float w = ws[k*AA + t];
            a0 += xb[k]*w; a1 += xb[ORIG+k]*w; a2 += xb[2*ORIG+k]*w; a3 += xb[3*ORIG+k]*w;
        }
        int nb = n0 + r4*4;
        g_x[(size_t)(nb+0)*AA + t] = a0;
        g_x[(size_t)(nb+1)*AA + t] = a1;
        g_x[(size_t)(nb+2)*AA + t] = a2;
        g_x[(size_t)(nb+3)*AA + t] = a3;
        __syncthreads();
    }
}

// P1/P2 projection — weights via LDG (L1/L2-resident), no weight smem.
__global__ __launch_bounds__(256)
void k_proj(const float* __restrict__ w, const float* __restrict__ bias) {
    __shared__ float xs[32*AA];
    int tid = threadIdx.x;
    int t = tid & 63, r8 = tid >> 6;
    ull bc = f2x_pack(bias[2*t], bias[2*t+1]);
    const ull* wv = (const ull*)w;
    const int NG = (NN + 31) / 32;
    for (int g = blockIdx.x; g < NG; g += gridDim.x) {
        int n0 = g * 32;
        int cnt = min(32, NN - n0);
        for (int i = tid; i < cnt*AA; i += 256) xs[i] = g_x[(size_t)n0*AA + i];
        __syncthreads();
        const float* xb = &xs[r8*8*AA];
        int nb = n0 + r8*8;
        ull p1[8], p2[8];
        #pragma unroll
        for (int r = 0; r < 8; r++) { p1[r] = bc; p2[r] = 0ull; }
        #pragma unroll 4
        for (int a = 0; a < AA; a++) {
            ull w1 = __ldg(&wv[a*64 + t]);
            ull w2 = __ldg(&wv[(AA+a)*64 + t]);
            #pragma unroll
            for (int r = 0; r < 8; r++) {
                float xf = xb[r*AA + a];
                ull xv = f2x_pack(xf, xf);
                p1[r] = f2x_fma(xv, w1, p1[r]);
                p2[r] = f2x_fma(xv, w2, p2[r]);
            }
        }
        #pragma unroll
        for (int r = 0; r < 8; r++) {
            if (nb + r < NN) {
                ((ull*)&g_P1[(size_t)(nb+r)*TWOA])[t] = p1[r];
                ((ull*)&g_P2[(size_t)(nb+r)*TWOA])[t] = p2[r];
            }
        }
        __syncthreads();
    }
}

// gated = P1[n] + P2[nbr] + nbr_fea @ W_edge ; bn1 stats (fp32 exact); store fp16.
__global__ __launch_bounds__(256, 3)
void k_edge(const float* __restrict__ we, const float* __restrict__ nbrf,
            const int* __restrict__ nidx, int layer) {
    __shared__ ulonglong2 wsv[NBRD*32];
    __shared__ float  nfs[8][6*NFS_STRIDE];
    __shared__ float  redS[TWOA], redQ[TWOA];
    int tid = threadIdx.x;
    {
        float* wf = (float*)wsv;
        for (int i = tid; i < NBRD*TWOA; i += 256) wf[i] = we[i];
    }
    __syncthreads();

    int w    = tid >> 5;
    int lane = tid & 31;
    int wg   = blockIdx.x * 8 + w;
    int nw   = gridDim.x * 8;

    ull s01 = 0ull, s23 = 0ull, q01 = 0ull, q23 = 0ull;

    const int NCH = RTOT/6;
    for (int ch = wg; ch < NCH; ch += nw) {
        int r0 = ch * 6;
        int n  = ch >> 1;
        const float* src = &nbrf[(size_t)r0 * NBRD];
        #pragma unroll
        for (int i = 0; i < 8; i++) {
            int p = lane + i*32;
            if (p < 6*NBRD) {
                int rr = p / NBRD, kk = p - rr*NBRD;
                nfs[w][rr*NFS_STRIDE + kk] = src[p];
            }
        }
        __syncwarp();
        ulonglong2 pa = ((const ulonglong2*)&g_P1[(size_t)n*TWOA])[lane];
        ull a01[6], a23[6];
        #pragma unroll
        for (int rr = 0; rr < 6; rr++) {
            int j = nidx[r0 + rr];
            ulonglong2 pb = ((const ulonglong2*)&g_P2[(size_t)j*TWOA])[lane];
            a01[rr] = f2x_add(pa.x, pb.x);
            a23[rr] = f2x_add(pa.y, pb.y);
        }
        #pragma unroll 1
        for (int kb = 0; kb < 40; kb += 4) {
            ulonglong2 w0 = wsv[(kb+0)*32 + lane];
            ulonglong2 w1 = wsv[(kb+1)*32 + lane];
            ulonglong2 w2 = wsv[(kb+2)*32 + lane];
            ulonglong2 w3 = wsv[(kb+3)*32 + lane];
            #pragma unroll
            for (int rr = 0; rr < 6; rr++) {
                float4 f = *(const float4*)&nfs[w][rr*NFS_STRIDE + kb];
                ull fx = f2x_pack(f.x, f.x);
                ull fy = f2x_pack(f.y, f.y);
                ull fz = f2x_pack(f.z, f.z);
                ull fw = f2x_pack(f.w, f.w);
                a01[rr] = f2x_fma(fx, w0.x, a01[rr]); a23[rr] = f2x_fma(fx, w0.y, a23[rr]);
                a01[rr] = f2x_fma(fy, w1.x, a01[rr]); a23[rr] = f2x_fma(fy, w1.y, a23[rr]);
                a01[rr] = f2x_fma(fz, w2.x, a01[rr]); a23[rr] = f2x_fma(fz, w2.y, a23[rr]);
                a01[rr] = f2x_fma(fw, w3.x, a01[rr]); a23[rr] = f2x_fma(fw, w3.y, a23[rr]);
            }
        }
        {
            ulonglong2 w4 = wsv[40*32 + lane];
            #pragma unroll
            for (int rr = 0; rr < 6; rr++) {
                float f = nfs[w][rr*NFS_STRIDE + 40];
                ull ff = f2x_pack(f, f);
                a01[rr] = f2x_fma(ff, w4.x, a01[rr]);
                a23[rr] = f2x_fma(ff, w4.y, a23[rr]);
            }
        }
        #pragma unroll
        for (int rr = 0; rr < 6; rr++) {
            float x0, x1, x2, x3;
            f2x_unpack(a01[rr], x0, x1);
            f2x_unpack(a23[rr], x2, x3);
            __half2 h0 = __floats2half2_rn(x0, x1);
            __half2 h1 = __floats2half2_rn(x2, x3);
            uint2 st; st.x = *(unsigned*)&h0; st.y = *(unsigned*)&h1;
            *(uint2*)&g_gatedh[(size_t)(r0+rr)*TWOA + lane*4] = st;
            s01 = f2x_add(s01, a01[rr]);
            s23 = f2x_add(s23, a23[rr]);
            q01 = f2x_fma(a01[rr], a01[rr], q01);
            q23 = f2x_fma(a23[rr], a23[rr], q23);
        }
        __syncwarp();
    }

    float s0,s1,s2,s3,q0,q1,q2,q3;
    f2x_unpack(s01, s0, s1); f2x_unpack(s23, s2, s3);
    f2x_unpack(q01, q0, q1); f2x_unpack(q23, q2, q3);

    if (tid < TWOA) { redS[tid] = 0.f; redQ[tid] = 0.f; }
    __syncthreads();
    int c = lane * 4;
    atomicAdd(&redS[c+0], s0); atomicAdd(&redQ[c+0], q0);
    atomicAdd(&redS[c+1], s1); atomicAdd(&redQ[c+1], q1);
    atomicAdd(&redS[c+2], s2); atomicAdd(&redQ[c+2], q2);
    atomicAdd(&redS[c+3], s3); atomicAdd(&redQ[c+3], q3);
    __syncthreads();
    if (tid < TWOA) {
        atomicAdd(&g_sum1[layer][tid],   (double)redS[tid]);
        atomicAdd(&g_sumsq1[layer][tid], (double)redQ[tid]);
    }
}

// bn1 (prologue) -> sigmoid*softplus -> sum over M ; bn2 stats.
// (R8 16x16 mapping; min 6 blocks/SM for latency hiding)
__global__ __launch_bounds__(256, 6)
void k_apply(int layer, const float* __restrict__ bn1g, const float* __restrict__ bn1b) {
    __shared__ float scS[TWOA], shS[TWOA];
    int tid = threadIdx.x;
    if (tid < TWOA) {
        double mean = g_sum1[layer][tid] * (1.0 / (double)RTOT);
        double var  = g_sumsq1[layer][tid] * (1.0 / (double)RTOT) - mean * mean;
        float istd = rsqrtf((float)var + EPSB);
        float sc = istd * bn1g[tid];
        scS[tid] = sc;
        shS[tid] = bn1b[tid] - (float)mean * sc;
    }
    __syncthreads();

    int tx = tid & 15, ty = tid >> 4;
    int c0 = tx * 4;
    float4 scF = *(const float4*)&scS[c0];
    float4 shF = *(const float4*)&shS[c0];
    float4 scC = *(const float4*)&scS[AA + c0];
    float4 shC = *(const float4*)&shS[AA + c0];
    float ls0=0,ls1=0,ls2=0,ls3=0, lq0=0,lq1=0,lq2=0,lq3=0;
    for (int n = blockIdx.x*16 + ty; n < NN; n += gridDim.x*16) {
        const uint2* gp = (const uint2*)&g_gatedh[(size_t)n*(MM*TWOA)];
        float s0=0,s1=0,s2=0,s3=0;
        #pragma unroll
        for (int m = 0; m < MM; m++) {
            uint2 fraw = gp[m*32 + tx];
            uint2 craw = gp[m*32 + 16 + tx];
            float2 f01 = __half22float2(*(__half2*)&fraw.x);
            float2 f23 = __half22float2(*(__half2*)&fraw.y);
            float2 c01 = __half22float2(*(__half2*)&craw.x);
            float2 c23 = __half22float2(*(__half2*)&craw.y);
            s0 += sigmoid_fast(f01.x*scF.x + shF.x) * softplus_fast(c01.x*scC.x + shC.x);
            s1 += sigmoid_fast(f01.y*scF.y + shF.y) * softplus_fast(c01.y*scC.y + shC.y);
            s2 += sigmoid_fast(f23.x*scF.z + shF.z) * softplus_fast(c23.x*scC.z + shC.z);
            s3 += sigmoid_fast(f23.y*scF.w + shF.w) * softplus_fast(c23.y*scC.w + shC.w);
        }
        float4 outv; outv.x=s0; outv.y=s1; outv.z=s2; outv.w=s3;
        *(float4*)&g_summed[(size_t)n*AA + c0] = outv;
        ls0+=s0; lq0+=s0*s0; ls1+=s1; lq1+=s1*s1;
        ls2+=s2; lq2+=s2*s2; ls3+=s3; lq3+=s3*s3;
    }
    __shared__ float rS[AA], rQ[AA];
    if (ty == 0) {
        #pragma unroll
        for (int i = 0; i < 4; i++) { rS[c0+i] = 0.f; rQ[c0+i] = 0.f; }
    }
    __syncthreads();
    atomicAdd(&rS[c0+0], ls0); atomicAdd(&rQ[c0+0], lq0);
    atomicAdd(&rS[c0+1], ls1); atomicAdd(&rQ[c0+1], lq1);
    atomicAdd(&rS[c0+2], ls2); atomicAdd(&rQ[c0+2], lq2);
    atomicAdd(&rS[c0+3], ls3); atomicAdd(&rQ[c0+3], lq3);
    __syncthreads();
    if (ty == 0) {
        #pragma unroll
        for (int i = 0; i < 4; i++) {
            atomicAdd(&g_sum2[layer][c0+i],   (double)rS[c0+i]);
            atomicAdd(&g_sumsq2[layer][c0+i], (double)rQ[c0+i]);
        }
    }
}

// x = softplus(x + bn2(summed))
__global__ __launch_bounds__(256)
void k_update(int layer, const float* __restrict__ bn2g, const float* __restrict__ bn2b) {
    __shared__ float sc2[AA], sh2[AA];
    int tid = threadIdx.x;
    if (tid < AA) {
        double mean = g_sum2[layer][tid] * (1.0 / (double)NN);
        double var  = g_sumsq2[layer][tid] * (1.0 / (double)NN) - mean * mean;
        float istd = rsqrtf((float)var + EPSB);
        float sc = istd * bn2g[tid];
        sc2[tid] = sc;
        sh2[tid] = bn2b[tid] - (float)mean * sc;
    }
    __syncthreads();
    const int NV = NN*AA/4;
    for (int i4 = blockIdx.x*256 + tid; i4 < NV; i4 += gridDim.x*256) {
        int c0 = (i4 & 15) * 4;
        float4 xv = *(const float4*)&g_x[(size_t)i4*4];
        float4 sv = *(const float4*)&g_summed[(size_t)i4*4];
        float4 o;
        o.x = softplus_fast(xv.x + sv.x*sc2[c0+0] + sh2[c0+0]);
        o.y = softplus_fast(xv.y + sv.y*sc2[c0+1] + sh2[c0+1]);
        o.z = softplus_fast(xv.z + sv.z*sc2[c0+2] + sh2[c0+2]);
        o.w = softplus_fast(xv.w + sv.w*sc2[c0+3] + sh2[c0+3]);
        *(float4*)&g_x[(size_t)i4*4] = o;
    }
}

// Final stage: warp owns groups of 4 atoms. 512 threads/block. (R14 best)
__global__ __launch_bounds__(512)
void k_final(const int* __restrict__ cidx,
             const float* __restrict__ adjw, const float* __restrict__ adjb,
             const float* __restrict__ fc1w, const float* __restrict__ fc1b,
             const float* __restrict__ afw,  const float* __restrict__ afb,
             float* __restrict__ out2) {
    extern __shared__ float smem[];
    float* Wt   = smem;                    // Wt[o][e][d] = adjw[o][d][e]
    float* afws = Wt + 6*64*64;
    float* vst  = afws + AA*ORIG;
    float* qsh  = vst + 16*4*64;
    int tid = threadIdx.x;
    int w = tid >> 5, lane = tid & 31;
    for (int i = tid; i < 6*64*64; i += 512) {
        int o = i >> 12, rem = i & 4095, e = rem >> 6, d = rem & 63;
        Wt[i] = adjw[o*4096 + d*64 + e];
    }
    for (int i = tid; i < AA*ORIG; i += 512) afws[i] = afw[i];
    __syncthreads();

    float* vw = &vst[w*4*64];
    float* qw = &qsh[w*4*6];
    ull bias0 = *(const ull*)&afb[2*lane];
    ull bias1 = (lane < 14) ? *(const ull*)&afb[64 + 2*lane] : 0ull;

    int nwarps = gridDim.x * 16;
    int wgid   = blockIdx.x * 16 + w;
    for (int g0 = wgid*4; g0 < BB*NPCC; g0 += nwarps*4) {
        #pragma unroll
        for (int t = 0; t < 4; t++) {
            int idx = cidx[g0 + t];
            vw[t*64 + lane]      = g_x[(size_t)idx*AA + lane];
            vw[t*64 + lane + 32] = g_x[(size_t)idx*AA + lane + 32];
        }
        __syncwarp();
        float2 rv[4];
        #pragma unroll
        for (int t = 0; t < 4; t++) rv[t] = *(const float2*)&vw[t*64 + 2*lane];

        ull acc[4][6];
        #pragma unroll
        for (int t = 0; t < 4; t++)
            #pragma unroll
            for (int o = 0; o < 6; o++) acc[t][o] = 0ull;
        #pragma unroll 2
        for (int e = 0; e < 64; e++) {
            ull wv[6];
            #pragma unroll
            for (int o = 0; o < 6; o++) wv[o] = *(const ull*)&Wt[(o*64 + e)*64 + 2*lane];
            #pragma unroll
            for (int t = 0; t < 4; t++) {
                float vb = vw[t*64 + e];
                ull vbb = f2x_pack(vb, vb);
                #pragma unroll
                for (int o = 0; o < 6; o++) acc[t][o] = f2x_fma(vbb, wv[o], acc[t][o]);
            }
        }
        #pragma unroll
        for (int t = 0; t < 4; t++) {
            #pragma unroll
            for (int o = 0; o < 6; o++) {
                float lo, hi; f2x_unpack(acc[t][o], lo, hi);
                float p = lo * rv[t].x + hi * rv[t].y;
                #pragma unroll
                for (int off = 16; off; off >>= 1) p += __shfl_xor_sync(0xffffffffu, p, off);
                if (lane == 0) qw[t*6 + o] = p + adjb[o];
            }
        }
        __syncwarp();
        if (lane < 4) {
            int t = lane;
            float q[6], q2[6];
            #pragma unroll
            for (int o = 0; o < 6; o++) q[o] = qw[t*6 + o];
            #pragma unroll
            for (int j = 0; j < 6; j++) {
                float a = fc1b[j];
                #pragma unroll
                for (int o = 0; o < 6; o++) a += q[o] * fc1w[o*6 + j];
                q2[j] = a;
            }
            float mx = q2[0];
            #pragma unroll
            for (int j = 1; j < 6; j++) mx = fmaxf(mx, q2[j]);
            float se = 0.f;
            #pragma unroll
            for (int j = 0; j < 6; j++) se += __expf(q2[j] - mx);
            float lse = __logf(se);
            #pragma unroll
            for (int j = 0; j < 6; j++) g_logp[(g0 + t)*6 + j] = q2[j] - mx - lse;
        }
        {
            ull acc0[4], acc1[4];
            #pragma unroll
            for (int t = 0; t < 4; t++) { acc0[t] = bias0; acc1[t] = bias1; }
            #pragma unroll 2
            for (int a = 0; a < 64; a++) {
                ull w0 = *(const ull*)&afws[a*ORIG + 2*lane];
                ull w1 = (lane < 14) ? *(const ull*)&afws[a*ORIG + 64 + 2*lane] : 0ull;
                #pragma unroll
                for (int t = 0; t < 4; t++) {
                    float va = vw[t*64 + a];
                    ull vv = f2x_pack(va, va);
                    acc0[t] = f2x_fma(vv, w0, acc0[t]);
                    acc1[t] = f2x_fma(vv, w1, acc1[t]);
                }
            }
            #pragma unroll
            for (int t = 0; t < 4; t++) {
                *(ull*)&out2[(size_t)(g0+t)*ORIG + 2*lane] = acc0[t];
                if (lane < 14) *(ull*)&out2[(size_t)(g0+t)*ORIG + 64 + 2*lane] = acc1[t];
            }
        }
        __syncwarp();
    }
}

// edge_prob broadcast — float4 stores
__global__ __launch_bounds__(256)
void k_edgeprob(float* __restrict__ out) {
    __shared__ float sh[NPCC*6];
    int b = blockIdx.x;
    for (int i = threadIdx.x; i < NPCC*6; i += 256) sh[i] = g_logp[b*NPCC*6 + i];
    __syncthreads();
    const float4* s4 = (const float4*)sh;
    float4* o4 = (float4*)(out + (size_t)b * (NPCC*NPCC*6));
    const int NT = NPCC*NPCC*6/4;
    for (int t = threadIdx.x; t < NT; t += 256) o4[t] = s4[t % 75];
}

// ---------------- host ----------------
extern "C" void kernel_launch(void* const* d_in, const int* in_sizes, int n_in,
                              void* d_out, int out_size) {
    const float* atom_fea = (const float*)d_in[0];
    const float* nbr_fea  = (const float*)d_in[1];
    const int*   nbr_idx  = (const int*)  d_in[2];
    const int*   cidx     = (const int*)  d_in[3];
    const float* emb_w    = (const float*)d_in[4];
    const float* fcw      = (const float*)d_in[5];
    const float* fcb      = (const float*)d_in[6];
    const float* bn1g     = (const float*)d_in[7];
    const float* bn1b     = (const float*)d_in[8];
    const float* bn2g     = (const float*)d_in[9];
    const float* bn2b     = (const float*)d_in[10];
    const float* adjw     = (const float*)d_in[11];
    const float* adjb     = (const float*)d_in[12];
    const float* fc1w     = (const float*)d_in[13];
    const float* fc1b     = (const float*)d_in[14];
    const float* afw      = (const float*)d_in[15];
    const float* afb      = (const float*)d_in[16];
    float* out = (float*)d_out;

    const int FINAL_SMEM = (6*64*64 + AA*ORIG + 16*4*64 + 16*4*6) * sizeof(float);
    cudaFuncSetAttribute(k_final, cudaFuncAttributeMaxDynamicSharedMemorySize, FINAL_SMEM);

    k_embed<<<1184, 256>>>(atom_fea, emb_w);

    for (int i = 0; i < 3; i++) {
        const float* w = fcw + i * (2*AA + NBRD) * TWOA;
        k_proj<<<592, 256>>>(w, fcb + i*TWOA);
        k_edge<<<444, 256>>>(w + 2*AA*TWOA, nbr_fea, nbr_idx, i);
        k_apply<<<1184, 256>>>(i, bn1g + i*TWOA, bn1b + i*TWOA);
        k_update<<<592, 256>>>(i, bn2g + i*AA, bn2b + i*AA);
    }

    float* out_atomfea = out + (size_t)BB * NPCC * NPCC * 6;
    k_final<<<148, 512, FINAL_SMEM>>>(cidx, adjw, adjb, fc1w, fc1b, afw, afb, out_atomfea);
    k_edgeprob<<<BB, 256>>>(out);
}